// round 13
// baseline (speedup 1.0000x reference)
#include <cuda_runtime.h>
#include <cuda_fp16.h>
#include <stdint.h>
#include <math.h>

#define CB 4
#define CS 2048
#define CD 1024
#define CH 16
#define CDK 64
#define CF 4096
#define MTOT (CB*CS)   // 8192
#define NQKV 3072

#define HF_SMEM (4 * 16384)       // fp16 gemm: 4 stages x (A 8KB + B 8KB) = 64KB
#define FA_SMEM 49152             // flash: Q 16KB + 2 KV stages x 16KB

// ---------------- scratch (device globals; no allocations allowed) ----------
__device__ float g_pr[(size_t)MTOT*CD];
__device__ float g_x1[(size_t)MTOT*CD];
__device__ float g_ff[(size_t)MTOT*CD];

__device__ __half g_x  [(size_t)MTOT*CD];
__device__ __half g_qkv[(size_t)MTOT*NQKV];
__device__ __half g_ao [(size_t)MTOT*CD];
__device__ __half g_x1h[(size_t)MTOT*CD];
__device__ __half g_hh [(size_t)MTOT*CF];

__device__ __half g_wqkv[(size_t)NQKV*CD];
__device__ __half g_wo[(size_t)CD*CD];
__device__ __half g_w1[(size_t)CF*CD];
__device__ __half g_w2[(size_t)CD*CF];
__device__ float g_bqkv[NQKV];

// ---------------- PTX helpers (non-'a' features only) ------------------------
__device__ __forceinline__ uint32_t smem_u32(const void* p) {
    uint32_t a;
    asm("{ .reg .u64 t; cvta.to.shared.u64 t, %1; cvt.u32.u64 %0, t; }" : "=r"(a) : "l"(p));
    return a;
}
__device__ __forceinline__ void cp16(uint32_t dst, const void* src) {
    asm volatile("cp.async.cg.shared.global [%0], [%1], 16;" :: "r"(dst), "l"(src));
}
template<int N> __device__ __forceinline__ void cpwait() {
    asm volatile("cp.async.wait_group %0;" :: "n"(N) : "memory");
}
__device__ __forceinline__ void ldsm4(uint32_t* r, uint32_t addr) {
    asm volatile("ldmatrix.sync.aligned.m8n8.x4.shared.b16 {%0,%1,%2,%3}, [%4];"
                 : "=r"(r[0]), "=r"(r[1]), "=r"(r[2]), "=r"(r[3]) : "r"(addr));
}
__device__ __forceinline__ void ldsm4t(uint32_t* r, uint32_t addr) {
    asm volatile("ldmatrix.sync.aligned.m8n8.x4.trans.shared.b16 {%0,%1,%2,%3}, [%4];"
                 : "=r"(r[0]), "=r"(r[1]), "=r"(r[2]), "=r"(r[3]) : "r"(addr));
}
__device__ __forceinline__ void mma16816h(float* c, const uint32_t* a, const uint32_t* b) {
    asm volatile(
        "mma.sync.aligned.m16n8k16.row.col.f32.f16.f16.f32 "
        "{%0,%1,%2,%3}, {%4,%5,%6,%7}, {%8,%9}, {%0,%1,%2,%3};"
        : "+f"(c[0]), "+f"(c[1]), "+f"(c[2]), "+f"(c[3])
        : "r"(a[0]), "r"(a[1]), "r"(a[2]), "r"(a[3]), "r"(b[0]), "r"(b[1]));
}
__device__ __forceinline__ float ex2f(float x) {
    float y; asm("ex2.approx.ftz.f32 %0, %1;" : "=f"(y) : "f"(x)); return y;
}
__device__ __forceinline__ uint32_t pack_hf2(float a, float b) {
    __half2 h; h.x = __float2half(a); h.y = __float2half(b);
    return *reinterpret_cast<uint32_t*>(&h);
}

// ---------------- mega prep kernel -------------------------------------------
// blocks [0,4096): convert x -> fp16. [4096,16384): weight fp16 transposes.
// [16384]: bias concat.
__global__ __launch_bounds__(256)
void prep_all(const float* __restrict__ x,
              const float* __restrict__ Wq, const float* __restrict__ Wk,
              const float* __restrict__ Wv, const float* __restrict__ Wo,
              const float* __restrict__ W1, const float* __restrict__ W2,
              const float* __restrict__ bq, const float* __restrict__ bk,
              const float* __restrict__ bv)
{
    __shared__ float t[32][33];
    const int blk = blockIdx.x;
    const int tid = threadIdx.x;

    if (blk < 4096) {                       // ---- convert x (2 float4 / thread)
        int i = blk * 512 + tid * 2;
        float4 v0 = reinterpret_cast<const float4*>(x)[i];
        float4 v1 = reinterpret_cast<const float4*>(x)[i + 1];
        __half2 a, b, c, d;
        a.x = __float2half(v0.x); a.y = __float2half(v0.y);
        b.x = __float2half(v0.z); b.y = __float2half(v0.w);
        c.x = __float2half(v1.x); c.y = __float2half(v1.y);
        d.x = __float2half(v1.z); d.y = __float2half(v1.w);
        reinterpret_cast<__half2*>(g_x)[2*i]     = a;
        reinterpret_cast<__half2*>(g_x)[2*i + 1] = b;
        reinterpret_cast<__half2*>(g_x)[2*i + 2] = c;
        reinterpret_cast<__half2*>(g_x)[2*i + 3] = d;
        return;
    }
    if (blk == 16384) {                     // ---- bias concat
        for (int i = tid; i < NQKV; i += 256)
            g_bqkv[i] = (i < 1024) ? bq[i] : (i < 2048) ? bk[i-1024] : bv[i-2048];
        return;
    }

    int b = blk - 4096;
    const float* W; __half* hT; int Kd, Nd;
    if      (b < 1024)  { W = Wq; hT = g_wqkv;              Kd = CD; Nd = CD; }
    else if (b < 2048)  { W = Wk; hT = g_wqkv + 1024u*CD;   Kd = CD; Nd = CD; b -= 1024; }
    else if (b < 3072)  { W = Wv; hT = g_wqkv + 2048u*CD;   Kd = CD; Nd = CD; b -= 2048; }
    else if (b < 4096)  { W = Wo; hT = g_wo; Kd = CD; Nd = CD; b -= 3072; }
    else if (b < 8192)  { W = W1; hT = g_w1; Kd = CD; Nd = CF; b -= 4096; }
    else                { W = W2; hT = g_w2; Kd = CF; Nd = CD; b -= 8192; }

    const int nb = Nd / 32;
    const int n0 = (b % nb) * 32, k0 = (b / nb) * 32;
    const int tx = tid & 31, ty = tid >> 5;
    for (int i = ty; i < 32; i += 8)
        t[i][tx] = W[(size_t)(k0 + i) * Nd + n0 + tx];
    __syncthreads();
    // vectorized half2 stores: thread e -> (n = n0 + e/16, kpair = e%16)
    for (int e = tid; e < 512; e += 256) {
        int kp = e & 15, i = e >> 4;
        __half2 v;
        v.x = __float2half(t[2*kp][i]);
        v.y = __float2half(t[2*kp + 1][i]);
        *reinterpret_cast<__half2*>(&hT[(size_t)(n0 + i) * Kd + k0 + 2*kp]) = v;
    }
}

// ---------------- plain fp16 HGEMM -------------------------------------------
// C[M,N] = A[M,K] @ B[N,K]^T + bias.  128 thr, 4 warps, 64x64 warp tiles,
// 4-stage ring (64KB).  EPI: 0 = fp32 C, 1 = fp16, 2 = relu + fp16
template<int EPI>
__global__ __launch_bounds__(128, 2)
void hgemm_fp16(const __half* __restrict__ A, const __half* __restrict__ B,
                const float* __restrict__ bias, float* __restrict__ C,
                __half* __restrict__ Ch, int M, int N, int K)
{
    extern __shared__ __align__(1024) char smraw[];
    const uint32_t sbase = smem_u32(smraw);

    const int tid  = threadIdx.x;
    const int lane = tid & 31;
    const int wid  = tid >> 5;
    const int warp_m = wid & 1;
    const int warp_n = wid >> 1;
    const int brow = blockIdx.y, bcol = blockIdx.x;

    const int lr = tid >> 2;
    const int lc = tid & 3;
    const int KC = K >> 5;

    uint32_t swr[4];
    size_t agr[4], bgr[4];
    #pragma unroll
    for (int rr = 0; rr < 4; ++rr) {
        int r = lr + rr * 32;
        int key = (r >> 1) & 3;
        swr[rr] = (uint32_t)r * 64u + (uint32_t)((lc ^ key) << 4);
        agr[rr] = (size_t)(brow * 128 + r) * (size_t)K;
        bgr[rr] = (size_t)(bcol * 128 + r) * (size_t)K;
    }

    uint32_t a_rb[4]; int a_key[4];
    #pragma unroll
    for (int mt = 0; mt < 4; ++mt) {
        int r = warp_m * 64 + mt * 16 + (lane & 15);
        a_rb[mt] = (uint32_t)r * 64u;
        a_key[mt] = (r >> 1) & 3;
    }
    const int a_ch = lane >> 4;
    uint32_t b_rb[4]; int b_key[4];
    #pragma unroll
    for (int np = 0; np < 4; ++np) {
        int r = warp_n * 64 + np * 16 + (lane & 7) + ((lane >> 4) & 1) * 8;
        b_rb[np] = (uint32_t)r * 64u;
        b_key[np] = (r >> 1) & 3;
    }
    const int b_ch = (lane >> 3) & 1;

    float acc[4][8][4];
    #pragma unroll
    for (int mt = 0; mt < 4; ++mt)
        #pragma unroll
        for (int nt = 0; nt < 8; ++nt)
            #pragma unroll
            for (int r = 0; r < 4; ++r) acc[mt][nt][r] = 0.f;

    auto load_stage = [&](int kk, int s) {
        const size_t ko = (size_t)kk * 32 + (size_t)lc * 8;
        const uint32_t st = sbase + (uint32_t)s * 16384u;
        #pragma unroll
        for (int rr = 0; rr < 4; ++rr) {
            cp16(st +         swr[rr], A + agr[rr] + ko);
            cp16(st + 8192u + swr[rr], B + bgr[rr] + ko);
        }
        asm volatile("cp.async.commit_group;" ::: "memory");
    };

    load_stage(0, 0);
    if (KC > 1) load_stage(1, 1);
    if (KC > 2) load_stage(2, 2);

    for (int t = 0; t < KC; ++t) {
        if (t + 2 < KC) cpwait<2>(); else if (t + 1 < KC) cpwait<1>(); else cpwait<0>();
        __syncthreads();
        if (t + 3 < KC) load_stage(t + 3, (t + 3) & 3);

        const uint32_t st = sbase + (uint32_t)(t & 3) * 16384u;
        #pragma unroll
        for (int ks = 0; ks < 2; ++ks) {
            uint32_t bf[4][4];
            #pragma unroll
            for (int np = 0; np < 4; ++np)
                ldsm4(bf[np], st + 8192u + b_rb[np] +
                      (uint32_t)((((ks << 1) + b_ch) ^ b_key[np]) << 4));
            uint32_t af[4][4];
            #pragma unroll
            for (int mt = 0; mt < 4; ++mt)
                ldsm4(af[mt], st + a_rb[mt] +
                      (uint32_t)((((ks << 1) + a_ch) ^ a_key[mt]) << 4));
            #pragma unroll
            for (int mt = 0; mt < 4; ++mt)
                #pragma unroll
                for (int nt = 0; nt < 8; ++nt)
                    mma16816h(acc[mt][nt], af[mt], &bf[nt >> 1][(nt & 1) * 2]);
        }
    }

    const int ng_base = bcol * 128 + warp_n * 64 + (lane & 3) * 2;
    const int mg_base = brow * 128 + warp_m * 64 + (lane >> 2);
    #pragma unroll
    for (int nt = 0; nt < 8; ++nt) {
        const int n = ng_base + nt * 8;
        const float2 bb = *reinterpret_cast<const float2*>(&bias[n]);
        #pragma unroll
        for (int mt = 0; mt < 4; ++mt) {
            const int m0 = mg_base + mt * 16;
            float v0 = acc[mt][nt][0] + bb.x, v1 = acc[mt][nt][1] + bb.y;
            float v2 = acc[mt][nt][2] + bb.x, v3 = acc[mt][nt][3] + bb.y;
            if (EPI == 2) {
                v0 = fmaxf(v0, 0.f); v1 = fmaxf(v1, 0.f);
                v2 = fmaxf(v2, 0.f); v3 = fmaxf(v3, 0.f);
            }
            if (EPI == 0) {
                float2 o0{v0, v1}, o1{v2, v3};
                *reinterpret_cast<float2*>(&C[(size_t)m0 * N + n])       = o0;
                *reinterpret_cast<float2*>(&C[(size_t)(m0 + 8) * N + n]) = o1;
            } else {
                *reinterpret_cast<uint32_t*>(&Ch[(size_t)m0 * N + n])       = pack_hf2(v0, v1);
                *reinterpret_cast<uint32_t*>(&Ch[(size_t)(m0 + 8) * N + n]) = pack_hf2(v2, v3);
            }
        }
    }
}

// ---------------- Flash attention, fp16, BQ=128 (causal) ---------------------
// 256 threads = 8 warps x 16 q-rows.  KV tile 64 rows, 2-stage ring.
__global__ __launch_bounds__(256)
void flash_hmma(const __half* __restrict__ QKV, __half* __restrict__ O)
{
    extern __shared__ __align__(1024) char smraw[];
    const uint32_t sb = smem_u32(smraw);
    const uint32_t QS = sb;                       // 128 x 128B = 16KB

    const int qt = (int)gridDim.x - 1 - (int)blockIdx.x;   // big tiles first
    const int b  = blockIdx.y >> 4, h = blockIdx.y & 15;
    const int tid = threadIdx.x, lane = tid & 31, warp = tid >> 5;

    const size_t qbase = (size_t)b * CS * NQKV + (size_t)h * CDK;
    const size_t obase = (size_t)b * CS * CD   + (size_t)h * CDK;

    // Q tile: 128 rows
    {
        const __half* g = QKV + qbase + (size_t)qt * 128 * NQKV;
        #pragma unroll
        for (int i = 0; i < 4; ++i) {
            int id = tid + i * 256;
            int r = id >> 3, c = id & 7;
            cp16(QS + (uint32_t)r * 128u + (uint32_t)((c ^ (r & 7)) << 4),
                 g + (size_t)r * NQKV + c * 8);
        }
    }
    auto load_kv = [&](int kt) {
        uint32_t s = sb + 16384u + (uint32_t)(kt & 1) * 16384u;
        const __half* gk = QKV + qbase + 1024 + (size_t)kt * 64 * NQKV;
        const __half* gv = QKV + qbase + 2048 + (size_t)kt * 64 * NQKV;
        #pragma unroll
        for (int i = 0; i < 2; ++i) {
            int id = tid + i * 256;
            int r = id >> 3, c = id & 7;
            uint32_t off = (uint32_t)r * 128u + (uint32_t)((c ^ (r & 7)) << 4);
            cp16(s +         off, gk + (size_t)r * NQKV + c * 8);
            cp16(s + 8192u + off, gv + (size_t)r * NQKV + c * 8);
        }
        asm volatile("cp.async.commit_group;" ::: "memory");
    };

    load_kv(0);
    cpwait<0>(); __syncthreads();

    uint32_t qf[4][4];
    {
        int r = warp * 16 + (lane & 15);
        uint32_t ro = (uint32_t)r * 128u;
        int key = r & 7;
        #pragma unroll
        for (int ks = 0; ks < 4; ++ks)
            ldsm4(qf[ks], QS + ro + (uint32_t)(((ks * 2 + (lane >> 4)) ^ key) << 4));
    }

    float m0 = -1e30f, m1 = -1e30f, l0 = 0.f, l1 = 0.f;
    float oacc[8][4];
    #pragma unroll
    for (int nt = 0; nt < 8; ++nt)
        #pragma unroll
        for (int r = 0; r < 4; ++r) oacc[nt][r] = 0.f;

    const float c1 = 0.18033688011112042f;
    const int grow = qt * 128 + warp * 16 + (lane >> 2);    // global q row (group 0)
    const int ktmax = 2 * qt + 1;

    for (int kt = 0; kt <= ktmax; ++kt) {
        if (kt + 1 <= ktmax) load_kv(kt + 1);
        if (kt > 0) {
            if (kt + 1 <= ktmax) cpwait<1>(); else cpwait<0>();
            __syncthreads();
        }
        const uint32_t KB = sb + 16384u + (uint32_t)(kt & 1) * 16384u;
        const uint32_t VB = KB + 8192u;

        float sacc[8][4];
        #pragma unroll
        for (int nt = 0; nt < 8; ++nt)
            #pragma unroll
            for (int r = 0; r < 4; ++r) sacc[nt][r] = 0.f;

        #pragma unroll
        for (int ks = 0; ks < 4; ++ks) {
            uint32_t bf[4][4];
            #pragma unroll
            for (int np = 0; np < 4; ++np) {
                int rr = np * 16 + (lane & 7) + ((lane >> 4) & 1) * 8;
                uint32_t chunk = (uint32_t)(ks * 2 + ((lane >> 3) & 1));
                ldsm4(bf[np], KB + (uint32_t)rr * 128u + ((chunk ^ (uint32_t)(rr & 7)) << 4));
            }
            #pragma unroll
            for (int nt = 0; nt < 8; ++nt)
                mma16816h(sacc[nt], qf[ks], &bf[nt >> 1][(nt & 1) * 2]);
        }

        // mask needed only when this kt tile can cross this warp's rows
        const bool diag = (kt * 64 + 63 > qt * 128 + warp * 16);
        float rm0 = -1e30f, rm1 = -1e30f;
        #pragma unroll
        for (int nt = 0; nt < 8; ++nt) {
            const int gc = kt * 64 + nt * 8 + 2 * (lane & 3);
            #pragma unroll
            for (int j = 0; j < 2; ++j) {
                float v = sacc[nt][j] * c1;
                if (diag && gc + j > grow) v = -1e30f;
                sacc[nt][j] = v; rm0 = fmaxf(rm0, v);
                float w = sacc[nt][2 + j] * c1;
                if (diag && gc + j > grow + 8) w = -1e30f;
                sacc[nt][2 + j] = w; rm1 = fmaxf(rm1, w);
            }
        }
        rm0 = fmaxf(rm0, __shfl_xor_sync(0xffffffffu, rm0, 1));
        rm0 = fmaxf(rm0, __shfl_xor_sync(0xffffffffu, rm0, 2));
        rm1 = fmaxf(rm1, __shfl_xor_sync(0xffffffffu, rm1, 1));
        rm1 = fmaxf(rm1, __shfl_xor_sync(0xffffffffu, rm1, 2));
        const float mn0 = fmaxf(m0, rm0), mn1 = fmaxf(m1, rm1);
        const float corr0 = ex2f(m0 - mn0), corr1 = ex2f(m1 - mn1);
        m0 = mn0; m1 = mn1;

        float ps0 = 0.f, ps1 = 0.f;
        uint32_t pf[4][4];
        #pragma unroll
        for (int nt = 0; nt < 8; ++nt) {
            float p0 = ex2f(sacc[nt][0] - m0);
            float p1 = ex2f(sacc[nt][1] - m0);
            float p2 = ex2f(sacc[nt][2] - m1);
            float p3 = ex2f(sacc[nt][3] - m1);
            float h0 = __half2float(__float2half(p0));
            float h1 = __half2float(__float2half(p1));
            float h2 = __half2float(__float2half(p2));
            float h3 = __half2float(__float2half(p3));
            ps0 += h0 + h1; ps1 += h2 + h3;
            const int kc = nt >> 1, base = (nt & 1) * 2;
            pf[kc][base]     = pack_hf2(h0, h1);
            pf[kc][base + 1] = pack_hf2(h2, h3);
        }
        ps0 += __shfl_xor_sync(0xffffffffu, ps0, 1);
        ps0 += __shfl_xor_sync(0xffffffffu, ps0, 2);
        ps1 += __shfl_xor_sync(0xffffffffu, ps1, 1);
        ps1 += __shfl_xor_sync(0xffffffffu, ps1, 2);
        l0 = l0 * corr0 + ps0;
        l1 = l1 * corr1 + ps1;

        #pragma unroll
        for (int nt = 0; nt < 8; ++nt) {
            oacc[nt][0] *= corr0; oacc[nt][1] *= corr0;
            oacc[nt][2] *= corr1; oacc[nt][3] *= corr1;
        }

        const int vj  = lane >> 3, vlp = lane & 7;
        #pragma unroll
        for (int kc = 0; kc < 4; ++kc) {
            const int vrow = kc * 16 + (vj & 1) * 8 + vlp;
            const uint32_t vro = (uint32_t)vrow * 128u;
            const uint32_t vkey = (uint32_t)(vrow & 7);
            uint32_t vf[4][4];
            #pragma unroll
            for (int vb = 0; vb < 4; ++vb) {
                uint32_t chunk = (uint32_t)(vb * 2 + (vj >> 1));
                ldsm4t(vf[vb], VB + vro + ((chunk ^ vkey) << 4));
            }
            #pragma unroll
            for (int nt = 0; nt < 8; ++nt)
                mma16816h(oacc[nt], pf[kc], &vf[nt >> 1][(nt & 1) * 2]);
        }
        __syncthreads();
    }

    const float inv0 = 1.f / l0, inv1 = 1.f / l1;
    const size_t row0 = obase + (size_t)grow * CD;
    const size_t row1 = row0 + (size_t)8 * CD;
    #pragma unroll
    for (int nt = 0; nt < 8; ++nt) {
        const int cb = nt * 8 + 2 * (lane & 3);
        *reinterpret_cast<uint32_t*>(&O[row0 + cb]) =
            pack_hf2(oacc[nt][0] * inv0, oacc[nt][1] * inv0);
        *reinterpret_cast<uint32_t*>(&O[row1 + cb]) =
            pack_hf2(oacc[nt][2] * inv1, oacc[nt][3] * inv1);
    }
}

// ---------------- residual + LayerNorm (optional fp16 output) ----------------
__global__ __launch_bounds__(256)
void residual_ln(const float* __restrict__ x, const float* __restrict__ r,
                 const float* __restrict__ gamma, const float* __restrict__ beta,
                 float* __restrict__ out, __half* __restrict__ outh)
{
    const int row = blockIdx.x;
    const int tid = threadIdx.x;
    const float4 a = reinterpret_cast<const float4*>(x + (size_t)row * CD)[tid];
    const float4 c = reinterpret_cast<const float4*>(r + (size_t)row * CD)[tid];
    float v0 = a.x + c.x, v1 = a.y + c.y, v2 = a.z + c.z, v3 = a.w + c.w;
    float s  = v0 + v1 + v2 + v3;
    float sq = v0 * v0 + v1 * v1 + v2 * v2 + v3 * v3;

    #pragma unroll
    for (int o = 16; o; o >>= 1) {
        s  += __shfl_xor_sync(0xffffffffu, s,  o);
        sq += __shfl_xor_sync(0xffffffffu, sq, o);
    }
    __shared__ float ss[8], sg[8];
    const int w = tid >> 5, lane = tid & 31;
    if (lane == 0) { ss[w] = s; sg[w] = sq; }
    __syncthreads();
    if (w == 0) {
        s  = (lane < 8) ? ss[lane] : 0.f;
        sq = (lane < 8) ? sg[lane] : 0.f;
        #pragma unroll
        for (int o = 4; o; o >>= 1) {
            s  += __shfl_xor_sync(0xffffffffu, s,  o);
            sq += __shfl_xor_sync(0xffffffffu, sq, o);
        }
        if (lane == 0) { ss[0] = s; sg[0] = sq; }
    }
    __syncthreads();
    s = ss[0]; sq = sg[0];

    const float mu  = s * (1.f / CD);
    const float var = sq * (1.f / CD) - mu * mu;
    const float inv = rsqrtf(var + 1e-5f);

    const float4 gv = reinterpret_cast<const float4*>(gamma)[tid];
    const float4 bv = reinterpret_cast<const float4*>(beta)[tid];
    float4 o4;
    o4.x = (v0 - mu) * inv * gv.x + bv.x;
    o4.y = (v1 - mu) * inv * gv.y + bv.y;
    o4.z = (v2 - mu) * inv * gv.z + bv.z;
    o4.w = (v3 - mu) * inv * gv.w + bv.w;
    reinterpret_cast<float4*>(out + (size_t)row * CD)[tid] = o4;

    if (outh) {
        __half2 h0, h1;
        h0.x = __float2half(o4.x); h0.y = __float2half(o4.y);
        h1.x = __float2half(o4.z); h1.y = __float2half(o4.w);
        reinterpret_cast<__half2*>(outh + (size_t)row * CD)[2*tid]   = h0;
        reinterpret_cast<__half2*>(outh + (size_t)row * CD)[2*tid+1] = h1;
    }
}

// ---------------- launch -----------------------------------------------------
extern "C" void kernel_launch(void* const* d_in, const int* in_sizes, int n_in,
                              void* d_out, int out_size)
{
    const float* x  = (const float*)d_in[0];
    const float* Wq = (const float*)d_in[2];
    const float* bq = (const float*)d_in[3];
    const float* Wk = (const float*)d_in[4];
    const float* bk = (const float*)d_in[5];
    const float* Wv = (const float*)d_in[6];
    const float* bv = (const float*)d_in[7];
    const float* Wo = (const float*)d_in[8];
    const float* bo = (const float*)d_in[9];
    const float* g1 = (const float*)d_in[10];
    const float* b1 = (const float*)d_in[11];
    const float* W1 = (const float*)d_in[12];
    const float* c1 = (const float*)d_in[13];
    const float* W2 = (const float*)d_in[14];
    const float* c2 = (const float*)d_in[15];
    const float* g2 = (const float*)d_in[16];
    const float* b2 = (const float*)d_in[17];
    float* out = (float*)d_out;

    float *pr, *x1, *ff, *bqkv;
    cudaGetSymbolAddress((void**)&pr, g_pr);
    cudaGetSymbolAddress((void**)&x1, g_x1);
    cudaGetSymbolAddress((void**)&ff, g_ff);
    cudaGetSymbolAddress((void**)&bqkv, g_bqkv);

    __half *xh,*qkv,*ao,*x1h,*hh,*wqkv,*wo,*w1,*w2;
    cudaGetSymbolAddress((void**)&xh,   g_x);
    cudaGetSymbolAddress((void**)&qkv,  g_qkv);
    cudaGetSymbolAddress((void**)&ao,   g_ao);
    cudaGetSymbolAddress((void**)&x1h,  g_x1h);
    cudaGetSymbolAddress((void**)&hh,   g_hh);
    cudaGetSymbolAddress((void**)&wqkv, g_wqkv);
    cudaGetSymbolAddress((void**)&wo,   g_wo);
    cudaGetSymbolAddress((void**)&w1,   g_w1);
    cudaGetSymbolAddress((void**)&w2,   g_w2);

    cudaFuncSetAttribute(flash_hmma, cudaFuncAttributeMaxDynamicSharedMemorySize, FA_SMEM);
    cudaFuncSetAttribute(hgemm_fp16<0>, cudaFuncAttributeMaxDynamicSharedMemorySize, HF_SMEM);
    cudaFuncSetAttribute(hgemm_fp16<1>, cudaFuncAttributeMaxDynamicSharedMemorySize, HF_SMEM);
    cudaFuncSetAttribute(hgemm_fp16<2>, cudaFuncAttributeMaxDynamicSharedMemorySize, HF_SMEM);

    prep_all<<<16385, 256>>>(x, Wq, Wk, Wv, Wo, W1, W2, bq, bk, bv);

    dim3 gQKV(NQKV / 128, MTOT / 128);
    dim3 gD(CD / 128, MTOT / 128);
    dim3 gF(CF / 128, MTOT / 128);

    hgemm_fp16<1><<<gQKV, 128, HF_SMEM>>>(xh, wqkv, bqkv, nullptr, qkv, MTOT, NQKV, CD);

    flash_hmma<<<dim3(CS / 128, CB * CH), 256, FA_SMEM>>>(qkv, ao);

    hgemm_fp16<0><<<gD, 128, HF_SMEM>>>(ao, wo, bo, pr, nullptr, MTOT, CD, CD);
    residual_ln<<<MTOT, 256>>>(x, pr, g1, b1, x1, x1h);

    hgemm_fp16<2><<<gF, 128, HF_SMEM>>>(x1h, w1, c1, nullptr, hh, MTOT, CF, CD);
    hgemm_fp16<0><<<gD, 128, HF_SMEM>>>(hh, w2, c2, ff, nullptr, MTOT, CD, CF);
    residual_ln<<<MTOT, 256>>>(x1, ff, g2, b2, out, nullptr);
}

// round 14
// speedup vs baseline: 1.0206x; 1.0206x over previous
#include <cuda_runtime.h>
#include <cuda_fp16.h>
#include <stdint.h>
#include <math.h>

#define CB 4
#define CS 2048
#define CD 1024
#define CH 16
#define CDK 64
#define CF 4096
#define MTOT (CB*CS)   // 8192
#define NQKV 3072

#define HF_SMEM (4 * 16384)        // fp16 gemm: 4 stages x (A 8KB + B 8KB) = 64KB
#define FA_SMEM (8192 + 2*32768)   // flash: Q 8KB + 2 KV stages x 32KB (K16+V16)

// ---------------- scratch (device globals; no allocations allowed) ----------
__device__ float g_pr[(size_t)MTOT*CD];
__device__ float g_x1[(size_t)MTOT*CD];
__device__ float g_ff[(size_t)MTOT*CD];

__device__ __half g_x  [(size_t)MTOT*CD];
__device__ __half g_qkv[(size_t)MTOT*NQKV];
__device__ __half g_ao [(size_t)MTOT*CD];
__device__ __half g_x1h[(size_t)MTOT*CD];
__device__ __half g_hh [(size_t)MTOT*CF];

__device__ __half g_wqkv[(size_t)NQKV*CD];
__device__ __half g_wo[(size_t)CD*CD];
__device__ __half g_w1[(size_t)CF*CD];
__device__ __half g_w2[(size_t)CD*CF];
__device__ float g_bqkv[NQKV];

// ---------------- PTX helpers (non-'a' features only) ------------------------
__device__ __forceinline__ uint32_t smem_u32(const void* p) {
    uint32_t a;
    asm("{ .reg .u64 t; cvta.to.shared.u64 t, %1; cvt.u32.u64 %0, t; }" : "=r"(a) : "l"(p));
    return a;
}
__device__ __forceinline__ void cp16(uint32_t dst, const void* src) {
    asm volatile("cp.async.cg.shared.global [%0], [%1], 16;" :: "r"(dst), "l"(src));
}
template<int N> __device__ __forceinline__ void cpwait() {
    asm volatile("cp.async.wait_group %0;" :: "n"(N) : "memory");
}
__device__ __forceinline__ void ldsm4(uint32_t* r, uint32_t addr) {
    asm volatile("ldmatrix.sync.aligned.m8n8.x4.shared.b16 {%0,%1,%2,%3}, [%4];"
                 : "=r"(r[0]), "=r"(r[1]), "=r"(r[2]), "=r"(r[3]) : "r"(addr));
}
__device__ __forceinline__ void ldsm4t(uint32_t* r, uint32_t addr) {
    asm volatile("ldmatrix.sync.aligned.m8n8.x4.trans.shared.b16 {%0,%1,%2,%3}, [%4];"
                 : "=r"(r[0]), "=r"(r[1]), "=r"(r[2]), "=r"(r[3]) : "r"(addr));
}
__device__ __forceinline__ void mma16816h(float* c, const uint32_t* a, const uint32_t* b) {
    asm volatile(
        "mma.sync.aligned.m16n8k16.row.col.f32.f16.f16.f32 "
        "{%0,%1,%2,%3}, {%4,%5,%6,%7}, {%8,%9}, {%0,%1,%2,%3};"
        : "+f"(c[0]), "+f"(c[1]), "+f"(c[2]), "+f"(c[3])
        : "r"(a[0]), "r"(a[1]), "r"(a[2]), "r"(a[3]), "r"(b[0]), "r"(b[1]));
}
__device__ __forceinline__ float ex2f(float x) {
    float y; asm("ex2.approx.ftz.f32 %0, %1;" : "=f"(y) : "f"(x)); return y;
}
__device__ __forceinline__ uint32_t pack_hf2(float a, float b) {
    __half2 h; h.x = __float2half(a); h.y = __float2half(b);
    return *reinterpret_cast<uint32_t*>(&h);
}

// ---------------- mega prep kernel -------------------------------------------
__global__ __launch_bounds__(256)
void prep_all(const float* __restrict__ x,
              const float* __restrict__ Wq, const float* __restrict__ Wk,
              const float* __restrict__ Wv, const float* __restrict__ Wo,
              const float* __restrict__ W1, const float* __restrict__ W2,
              const float* __restrict__ bq, const float* __restrict__ bk,
              const float* __restrict__ bv)
{
    __shared__ float t[32][33];
    const int blk = blockIdx.x;
    const int tid = threadIdx.x;

    if (blk < 4096) {                       // ---- convert x (2 float4 / thread)
        int i = blk * 512 + tid * 2;
        float4 v0 = reinterpret_cast<const float4*>(x)[i];
        float4 v1 = reinterpret_cast<const float4*>(x)[i + 1];
        __half2 a, b, c, d;
        a.x = __float2half(v0.x); a.y = __float2half(v0.y);
        b.x = __float2half(v0.z); b.y = __float2half(v0.w);
        c.x = __float2half(v1.x); c.y = __float2half(v1.y);
        d.x = __float2half(v1.z); d.y = __float2half(v1.w);
        reinterpret_cast<__half2*>(g_x)[2*i]     = a;
        reinterpret_cast<__half2*>(g_x)[2*i + 1] = b;
        reinterpret_cast<__half2*>(g_x)[2*i + 2] = c;
        reinterpret_cast<__half2*>(g_x)[2*i + 3] = d;
        return;
    }
    if (blk == 16384) {                     // ---- bias concat
        for (int i = tid; i < NQKV; i += 256)
            g_bqkv[i] = (i < 1024) ? bq[i] : (i < 2048) ? bk[i-1024] : bv[i-2048];
        return;
    }

    int b = blk - 4096;
    const float* W; __half* hT; int Kd, Nd;
    if      (b < 1024)  { W = Wq; hT = g_wqkv;              Kd = CD; Nd = CD; }
    else if (b < 2048)  { W = Wk; hT = g_wqkv + 1024u*CD;   Kd = CD; Nd = CD; b -= 1024; }
    else if (b < 3072)  { W = Wv; hT = g_wqkv + 2048u*CD;   Kd = CD; Nd = CD; b -= 2048; }
    else if (b < 4096)  { W = Wo; hT = g_wo; Kd = CD; Nd = CD; b -= 3072; }
    else if (b < 8192)  { W = W1; hT = g_w1; Kd = CD; Nd = CF; b -= 4096; }
    else                { W = W2; hT = g_w2; Kd = CF; Nd = CD; b -= 8192; }

    const int nb = Nd / 32;
    const int n0 = (b % nb) * 32, k0 = (b / nb) * 32;
    const int tx = tid & 31, ty = tid >> 5;
    for (int i = ty; i < 32; i += 8)
        t[i][tx] = W[(size_t)(k0 + i) * Nd + n0 + tx];
    __syncthreads();
    for (int e = tid; e < 512; e += 256) {
        int kp = e & 15, i = e >> 4;
        __half2 v;
        v.x = __float2half(t[2*kp][i]);
        v.y = __float2half(t[2*kp + 1][i]);
        *reinterpret_cast<__half2*>(&hT[(size_t)(n0 + i) * Kd + k0 + 2*kp]) = v;
    }
}

// ---------------- plain fp16 HGEMM (unchanged from R12) ----------------------
template<int EPI>
__global__ __launch_bounds__(128, 2)
void hgemm_fp16(const __half* __restrict__ A, const __half* __restrict__ B,
                const float* __restrict__ bias, float* __restrict__ C,
                __half* __restrict__ Ch, int M, int N, int K)
{
    extern __shared__ __align__(1024) char smraw[];
    const uint32_t sbase = smem_u32(smraw);

    const int tid  = threadIdx.x;
    const int lane = tid & 31;
    const int wid  = tid >> 5;
    const int warp_m = wid & 1;
    const int warp_n = wid >> 1;
    const int brow = blockIdx.y, bcol = blockIdx.x;

    const int lr = tid >> 2;
    const int lc = tid & 3;
    const int KC = K >> 5;

    uint32_t swr[4];
    size_t agr[4], bgr[4];
    #pragma unroll
    for (int rr = 0; rr < 4; ++rr) {
        int r = lr + rr * 32;
        int key = (r >> 1) & 3;
        swr[rr] = (uint32_t)r * 64u + (uint32_t)((lc ^ key) << 4);
        agr[rr] = (size_t)(brow * 128 + r) * (size_t)K;
        bgr[rr] = (size_t)(bcol * 128 + r) * (size_t)K;
    }

    uint32_t a_rb[4]; int a_key[4];
    #pragma unroll
    for (int mt = 0; mt < 4; ++mt) {
        int r = warp_m * 64 + mt * 16 + (lane & 15);
        a_rb[mt] = (uint32_t)r * 64u;
        a_key[mt] = (r >> 1) & 3;
    }
    const int a_ch = lane >> 4;
    uint32_t b_rb[4]; int b_key[4];
    #pragma unroll
    for (int np = 0; np < 4; ++np) {
        int r = warp_n * 64 + np * 16 + (lane & 7) + ((lane >> 4) & 1) * 8;
        b_rb[np] = (uint32_t)r * 64u;
        b_key[np] = (r >> 1) & 3;
    }
    const int b_ch = (lane >> 3) & 1;

    float acc[4][8][4];
    #pragma unroll
    for (int mt = 0; mt < 4; ++mt)
        #pragma unroll
        for (int nt = 0; nt < 8; ++nt)
            #pragma unroll
            for (int r = 0; r < 4; ++r) acc[mt][nt][r] = 0.f;

    auto load_stage = [&](int kk, int s) {
        const size_t ko = (size_t)kk * 32 + (size_t)lc * 8;
        const uint32_t st = sbase + (uint32_t)s * 16384u;
        #pragma unroll
        for (int rr = 0; rr < 4; ++rr) {
            cp16(st +         swr[rr], A + agr[rr] + ko);
            cp16(st + 8192u + swr[rr], B + bgr[rr] + ko);
        }
        asm volatile("cp.async.commit_group;" ::: "memory");
    };

    load_stage(0, 0);
    if (KC > 1) load_stage(1, 1);
    if (KC > 2) load_stage(2, 2);

    for (int t = 0; t < KC; ++t) {
        if (t + 2 < KC) cpwait<2>(); else if (t + 1 < KC) cpwait<1>(); else cpwait<0>();
        __syncthreads();
        if (t + 3 < KC) load_stage(t + 3, (t + 3) & 3);

        const uint32_t st = sbase + (uint32_t)(t & 3) * 16384u;
        #pragma unroll
        for (int ks = 0; ks < 2; ++ks) {
            uint32_t bf[4][4];
            #pragma unroll
            for (int np = 0; np < 4; ++np)
                ldsm4(bf[np], st + 8192u + b_rb[np] +
                      (uint32_t)((((ks << 1) + b_ch) ^ b_key[np]) << 4));
            uint32_t af[4][4];
            #pragma unroll
            for (int mt = 0; mt < 4; ++mt)
                ldsm4(af[mt], st + a_rb[mt] +
                      (uint32_t)((((ks << 1) + a_ch) ^ a_key[mt]) << 4));
            #pragma unroll
            for (int mt = 0; mt < 4; ++mt)
                #pragma unroll
                for (int nt = 0; nt < 8; ++nt)
                    mma16816h(acc[mt][nt], af[mt], &bf[nt >> 1][(nt & 1) * 2]);
        }
    }

    const int ng_base = bcol * 128 + warp_n * 64 + (lane & 3) * 2;
    const int mg_base = brow * 128 + warp_m * 64 + (lane >> 2);
    #pragma unroll
    for (int nt = 0; nt < 8; ++nt) {
        const int n = ng_base + nt * 8;
        const float2 bb = *reinterpret_cast<const float2*>(&bias[n]);
        #pragma unroll
        for (int mt = 0; mt < 4; ++mt) {
            const int m0 = mg_base + mt * 16;
            float v0 = acc[mt][nt][0] + bb.x, v1 = acc[mt][nt][1] + bb.y;
            float v2 = acc[mt][nt][2] + bb.x, v3 = acc[mt][nt][3] + bb.y;
            if (EPI == 2) {
                v0 = fmaxf(v0, 0.f); v1 = fmaxf(v1, 0.f);
                v2 = fmaxf(v2, 0.f); v3 = fmaxf(v3, 0.f);
            }
            if (EPI == 0) {
                float2 o0{v0, v1}, o1{v2, v3};
                *reinterpret_cast<float2*>(&C[(size_t)m0 * N + n])       = o0;
                *reinterpret_cast<float2*>(&C[(size_t)(m0 + 8) * N + n]) = o1;
            } else {
                *reinterpret_cast<uint32_t*>(&Ch[(size_t)m0 * N + n])       = pack_hf2(v0, v1);
                *reinterpret_cast<uint32_t*>(&Ch[(size_t)(m0 + 8) * N + n]) = pack_hf2(v2, v3);
            }
        }
    }
}

// ---------------- Flash attention, fp16, BQ=64 / BKV=128 (causal) ------------
// 128 threads = 4 warps x 16 q-rows.  KV tile 128 rows -> per-iteration
// softmax/barrier overheads halved per unit of mma work.
__global__ __launch_bounds__(128)
void flash_hmma(const __half* __restrict__ QKV, __half* __restrict__ O)
{
    extern __shared__ __align__(1024) char smraw[];
    const uint32_t sb = smem_u32(smraw);
    const uint32_t QS = sb;                       // 64 x 128B = 8KB

    const int qt = (int)gridDim.x - 1 - (int)blockIdx.x;   // big tiles first
    const int b  = blockIdx.y >> 4, h = blockIdx.y & 15;
    const int tid = threadIdx.x, lane = tid & 31, warp = tid >> 5;

    const size_t qbase = (size_t)b * CS * NQKV + (size_t)h * CDK;
    const size_t obase = (size_t)b * CS * CD   + (size_t)h * CDK;

    // Q tile (64 rows)
    {
        const __half* g = QKV + qbase + (size_t)qt * 64 * NQKV;
        #pragma unroll
        for (int i = 0; i < 4; ++i) {
            int id = tid + i * 128;
            int r = id >> 3, c = id & 7;
            cp16(QS + (uint32_t)r * 128u + (uint32_t)((c ^ (r & 7)) << 4),
                 g + (size_t)r * NQKV + c * 8);
        }
    }
    // KV tile: 128 K rows + 128 V rows = 32KB
    auto load_kv = [&](int kt) {
        uint32_t s = sb + 8192u + (uint32_t)(kt & 1) * 32768u;
        const __half* gk = QKV + qbase + 1024 + (size_t)kt * 128 * NQKV;
        const __half* gv = QKV + qbase + 2048 + (size_t)kt * 128 * NQKV;
        #pragma unroll
        for (int i = 0; i < 8; ++i) {
            int id = tid + i * 128;
            int r = id >> 3, c = id & 7;
            uint32_t off = (uint32_t)r * 128u + (uint32_t)((c ^ (r & 7)) << 4);
            cp16(s +          off, gk + (size_t)r * NQKV + c * 8);
            cp16(s + 16384u + off, gv + (size_t)r * NQKV + c * 8);
        }
        asm volatile("cp.async.commit_group;" ::: "memory");
    };

    load_kv(0);
    cpwait<0>(); __syncthreads();

    uint32_t qf[4][4];
    {
        int r = warp * 16 + (lane & 15);
        uint32_t ro = (uint32_t)r * 128u;
        int key = r & 7;
        #pragma unroll
        for (int ks = 0; ks < 4; ++ks)
            ldsm4(qf[ks], QS + ro + (uint32_t)(((ks * 2 + (lane >> 4)) ^ key) << 4));
    }

    float m0 = -1e30f, m1 = -1e30f, l0 = 0.f, l1 = 0.f;
    float oacc[8][4];
    #pragma unroll
    for (int nt = 0; nt < 8; ++nt)
        #pragma unroll
        for (int r = 0; r < 4; ++r) oacc[nt][r] = 0.f;

    const float c1 = 0.18033688011112042f;
    const int grow = qt * 64 + warp * 16 + (lane >> 2);
    const int ktmax = qt >> 1;                    // KV tiles of 128 rows

    for (int kt = 0; kt <= ktmax; ++kt) {
        if (kt + 1 <= ktmax) load_kv(kt + 1);
        if (kt > 0) {
            if (kt + 1 <= ktmax) cpwait<1>(); else cpwait<0>();
            __syncthreads();
        }
        const uint32_t KB = sb + 8192u + (uint32_t)(kt & 1) * 32768u;
        const uint32_t VB = KB + 16384u;

        float sacc[16][4];
        #pragma unroll
        for (int nt = 0; nt < 16; ++nt)
            #pragma unroll
            for (int r = 0; r < 4; ++r) sacc[nt][r] = 0.f;

        #pragma unroll
        for (int ks = 0; ks < 4; ++ks) {
            uint32_t bf[8][4];
            #pragma unroll
            for (int np = 0; np < 8; ++np) {
                int rr = np * 16 + (lane & 7) + ((lane >> 4) & 1) * 8;
                uint32_t chunk = (uint32_t)(ks * 2 + ((lane >> 3) & 1));
                ldsm4(bf[np], KB + (uint32_t)rr * 128u + ((chunk ^ (uint32_t)(rr & 7)) << 4));
            }
            #pragma unroll
            for (int nt = 0; nt < 16; ++nt)
                mma16816h(sacc[nt], qf[ks], &bf[nt >> 1][(nt & 1) * 2]);
        }

        const bool diag = (kt * 128 + 127 > qt * 64 + warp * 16);
        float rm0 = -1e30f, rm1 = -1e30f;
        #pragma unroll
        for (int nt = 0; nt < 16; ++nt) {
            const int gc = kt * 128 + nt * 8 + 2 * (lane & 3);
            #pragma unroll
            for (int j = 0; j < 2; ++j) {
                float v = sacc[nt][j] * c1;
                if (diag && gc + j > grow) v = -1e30f;
                sacc[nt][j] = v; rm0 = fmaxf(rm0, v);
                float w = sacc[nt][2 + j] * c1;
                if (diag && gc + j > grow + 8) w = -1e30f;
                sacc[nt][2 + j] = w; rm1 = fmaxf(rm1, w);
            }
        }
        rm0 = fmaxf(rm0, __shfl_xor_sync(0xffffffffu, rm0, 1));
        rm0 = fmaxf(rm0, __shfl_xor_sync(0xffffffffu, rm0, 2));
        rm1 = fmaxf(rm1, __shfl_xor_sync(0xffffffffu, rm1, 1));
        rm1 = fmaxf(rm1, __shfl_xor_sync(0xffffffffu, rm1, 2));
        const float mn0 = fmaxf(m0, rm0), mn1 = fmaxf(m1, rm1);
        const float corr0 = ex2f(m0 - mn0), corr1 = ex2f(m1 - mn1);
        m0 = mn0; m1 = mn1;

        float ps0 = 0.f, ps1 = 0.f;
        uint32_t pf[8][4];
        #pragma unroll
        for (int nt = 0; nt < 16; ++nt) {
            float p0 = ex2f(sacc[nt][0] - m0);
            float p1 = ex2f(sacc[nt][1] - m0);
            float p2 = ex2f(sacc[nt][2] - m1);
            float p3 = ex2f(sacc[nt][3] - m1);
            float h0 = __half2float(__float2half(p0));
            float h1 = __half2float(__float2half(p1));
            float h2 = __half2float(__float2half(p2));
            float h3 = __half2float(__float2half(p3));
            ps0 += h0 + h1; ps1 += h2 + h3;
            const int kc = nt >> 1, base = (nt & 1) * 2;
            pf[kc][base]     = pack_hf2(h0, h1);
            pf[kc][base + 1] = pack_hf2(h2, h3);
        }
        ps0 += __shfl_xor_sync(0xffffffffu, ps0, 1);
        ps0 += __shfl_xor_sync(0xffffffffu, ps0, 2);
        ps1 += __shfl_xor_sync(0xffffffffu, ps1, 1);
        ps1 += __shfl_xor_sync(0xffffffffu, ps1, 2);
        l0 = l0 * corr0 + ps0;
        l1 = l1 * corr1 + ps1;

        #pragma unroll
        for (int nt = 0; nt < 8; ++nt) {
            oacc[nt][0] *= corr0; oacc[nt][1] *= corr0;
            oacc[nt][2] *= corr1; oacc[nt][3] *= corr1;
        }

        const int vj  = lane >> 3, vlp = lane & 7;
        #pragma unroll
        for (int kc = 0; kc < 8; ++kc) {
            const int vrow = kc * 16 + (vj & 1) * 8 + vlp;
            const uint32_t vro = (uint32_t)vrow * 128u;
            const uint32_t vkey = (uint32_t)(vrow & 7);
            uint32_t vf[4][4];
            #pragma unroll
            for (int vb = 0; vb < 4; ++vb) {
                uint32_t chunk = (uint32_t)(vb * 2 + (vj >> 1));
                ldsm4t(vf[vb], VB + vro + ((chunk ^ vkey) << 4));
            }
            #pragma unroll
            for (int nt = 0; nt < 8; ++nt)
                mma16816h(oacc[nt], pf[kc], &vf[nt >> 1][(nt & 1) * 2]);
        }
        __syncthreads();
    }

    const float inv0 = 1.f / l0, inv1 = 1.f / l1;
    const size_t row0 = obase + (size_t)grow * CD;
    const size_t row1 = row0 + (size_t)8 * CD;
    #pragma unroll
    for (int nt = 0; nt < 8; ++nt) {
        const int cb = nt * 8 + 2 * (lane & 3);
        *reinterpret_cast<uint32_t*>(&O[row0 + cb]) =
            pack_hf2(oacc[nt][0] * inv0, oacc[nt][1] * inv0);
        *reinterpret_cast<uint32_t*>(&O[row1 + cb]) =
            pack_hf2(oacc[nt][2] * inv1, oacc[nt][3] * inv1);
    }
}

// ---------------- residual + LayerNorm (optional fp16 output) ----------------
__global__ __launch_bounds__(256)
void residual_ln(const float* __restrict__ x, const float* __restrict__ r,
                 const float* __restrict__ gamma, const float* __restrict__ beta,
                 float* __restrict__ out, __half* __restrict__ outh)
{
    const int row = blockIdx.x;
    const int tid = threadIdx.x;
    const float4 a = reinterpret_cast<const float4*>(x + (size_t)row * CD)[tid];
    const float4 c = reinterpret_cast<const float4*>(r + (size_t)row * CD)[tid];
    float v0 = a.x + c.x, v1 = a.y + c.y, v2 = a.z + c.z, v3 = a.w + c.w;
    float s  = v0 + v1 + v2 + v3;
    float sq = v0 * v0 + v1 * v1 + v2 * v2 + v3 * v3;

    #pragma unroll
    for (int o = 16; o; o >>= 1) {
        s  += __shfl_xor_sync(0xffffffffu, s,  o);
        sq += __shfl_xor_sync(0xffffffffu, sq, o);
    }
    __shared__ float ss[8], sg[8];
    const int w = tid >> 5, lane = tid & 31;
    if (lane == 0) { ss[w] = s; sg[w] = sq; }
    __syncthreads();
    if (w == 0) {
        s  = (lane < 8) ? ss[lane] : 0.f;
        sq = (lane < 8) ? sg[lane] : 0.f;
        #pragma unroll
        for (int o = 4; o; o >>= 1) {
            s  += __shfl_xor_sync(0xffffffffu, s,  o);
            sq += __shfl_xor_sync(0xffffffffu, sq, o);
        }
        if (lane == 0) { ss[0] = s; sg[0] = sq; }
    }
    __syncthreads();
    s = ss[0]; sq = sg[0];

    const float mu  = s * (1.f / CD);
    const float var = sq * (1.f / CD) - mu * mu;
    const float inv = rsqrtf(var + 1e-5f);

    const float4 gv = reinterpret_cast<const float4*>(gamma)[tid];
    const float4 bv = reinterpret_cast<const float4*>(beta)[tid];
    float4 o4;
    o4.x = (v0 - mu) * inv * gv.x + bv.x;
    o4.y = (v1 - mu) * inv * gv.y + bv.y;
    o4.z = (v2 - mu) * inv * gv.z + bv.z;
    o4.w = (v3 - mu) * inv * gv.w + bv.w;
    reinterpret_cast<float4*>(out + (size_t)row * CD)[tid] = o4;

    if (outh) {
        __half2 h0, h1;
        h0.x = __float2half(o4.x); h0.y = __float2half(o4.y);
        h1.x = __float2half(o4.z); h1.y = __float2half(o4.w);
        reinterpret_cast<__half2*>(outh + (size_t)row * CD)[2*tid]   = h0;
        reinterpret_cast<__half2*>(outh + (size_t)row * CD)[2*tid+1] = h1;
    }
}

// ---------------- launch -----------------------------------------------------
extern "C" void kernel_launch(void* const* d_in, const int* in_sizes, int n_in,
                              void* d_out, int out_size)
{
    const float* x  = (const float*)d_in[0];
    const float* Wq = (const float*)d_in[2];
    const float* bq = (const float*)d_in[3];
    const float* Wk = (const float*)d_in[4];
    const float* bk = (const float*)d_in[5];
    const float* Wv = (const float*)d_in[6];
    const float* bv = (const float*)d_in[7];
    const float* Wo = (const float*)d_in[8];
    const float* bo = (const float*)d_in[9];
    const float* g1 = (const float*)d_in[10];
    const float* b1 = (const float*)d_in[11];
    const float* W1 = (const float*)d_in[12];
    const float* c1 = (const float*)d_in[13];
    const float* W2 = (const float*)d_in[14];
    const float* c2 = (const float*)d_in[15];
    const float* g2 = (const float*)d_in[16];
    const float* b2 = (const float*)d_in[17];
    float* out = (float*)d_out;

    float *pr, *x1, *ff, *bqkv;
    cudaGetSymbolAddress((void**)&pr, g_pr);
    cudaGetSymbolAddress((void**)&x1, g_x1);
    cudaGetSymbolAddress((void**)&ff, g_ff);
    cudaGetSymbolAddress((void**)&bqkv, g_bqkv);

    __half *xh,*qkv,*ao,*x1h,*hh,*wqkv,*wo,*w1,*w2;
    cudaGetSymbolAddress((void**)&xh,   g_x);
    cudaGetSymbolAddress((void**)&qkv,  g_qkv);
    cudaGetSymbolAddress((void**)&ao,   g_ao);
    cudaGetSymbolAddress((void**)&x1h,  g_x1h);
    cudaGetSymbolAddress((void**)&hh,   g_hh);
    cudaGetSymbolAddress((void**)&wqkv, g_wqkv);
    cudaGetSymbolAddress((void**)&wo,   g_wo);
    cudaGetSymbolAddress((void**)&w1,   g_w1);
    cudaGetSymbolAddress((void**)&w2,   g_w2);

    cudaFuncSetAttribute(flash_hmma, cudaFuncAttributeMaxDynamicSharedMemorySize, FA_SMEM);
    cudaFuncSetAttribute(hgemm_fp16<0>, cudaFuncAttributeMaxDynamicSharedMemorySize, HF_SMEM);
    cudaFuncSetAttribute(hgemm_fp16<1>, cudaFuncAttributeMaxDynamicSharedMemorySize, HF_SMEM);
    cudaFuncSetAttribute(hgemm_fp16<2>, cudaFuncAttributeMaxDynamicSharedMemorySize, HF_SMEM);

    prep_all<<<16385, 256>>>(x, Wq, Wk, Wv, Wo, W1, W2, bq, bk, bv);

    dim3 gQKV(NQKV / 128, MTOT / 128);
    dim3 gD(CD / 128, MTOT / 128);
    dim3 gF(CF / 128, MTOT / 128);

    hgemm_fp16<1><<<gQKV, 128, HF_SMEM>>>(xh, wqkv, bqkv, nullptr, qkv, MTOT, NQKV, CD);

    flash_hmma<<<dim3(CS / 64, CB * CH), 128, FA_SMEM>>>(qkv, ao);

    hgemm_fp16<0><<<gD, 128, HF_SMEM>>>(ao, wo, bo, pr, nullptr, MTOT, CD, CD);
    residual_ln<<<MTOT, 256>>>(x, pr, g1, b1, x1, x1h);

    hgemm_fp16<2><<<gF, 128, HF_SMEM>>>(x1h, w1, c1, nullptr, hh, MTOT, CF, CD);
    hgemm_fp16<0><<<gD, 128, HF_SMEM>>>(hh, w2, c2, ff, nullptr, MTOT, CD, CF);
    residual_ln<<<MTOT, 256>>>(x1, ff, g2, b2, out, nullptr);
}